// round 14
// baseline (speedup 1.0000x reference)
#include <cuda_runtime.h>
#include <cuda_fp16.h>
#include <stdint.h>
#include <math.h>

// Problem constants
#define BB 16
#define CC 512
#define NN 2304      // 48*48
#define II 64

// ---------------- scratch (static device globals; no allocation) ----------------
__device__ float  g_qk[(size_t)BB * 128 * NN];        //  19 MB fp32 [q(0:64); k(64:128)][n]
__device__ __half g_qth[(size_t)BB * NN * II];        // 4.7 MB qT hi [n][i]
__device__ __half g_qtl[(size_t)BB * NN * II];        // 4.7 MB qT lo
__device__ __half g_kth[(size_t)BB * NN * II];        // 4.7 MB kT hi [m][i]
__device__ __half g_ktl[(size_t)BB * NN * II];        // 4.7 MB kT lo
__device__ float  g_s[(size_t)BB * NN * NN];          // 324 MB fp32 logits S
__device__ __half g_ph[(size_t)BB * NN * NN];         // 162 MB fp16 softmax P
__device__ __half g_vh[(size_t)BB * CC * NN];         //  36 MB fp16 V
__device__ __half g_xth[(size_t)BB * NN * CC];        //  74 MB fp16 xT [n][c]
__device__ float  g_wqk[128 * CC];                    // [Wq; Wk] concat fp32
__device__ __half g_wvh[CC * CC];                     // Wv fp16

// =====================================================================
// helpers
// =====================================================================
__device__ __forceinline__ uint32_t smem_u32(const void* p) {
    uint32_t a;
    asm("{ .reg .u64 t; cvta.to.shared.u64 t, %1; cvt.u32.u64 %0, t; }"
        : "=r"(a) : "l"(p));
    return a;
}

__device__ __forceinline__ void cp_async16(uint32_t saddr, const void* gptr) {
    asm volatile("cp.async.cg.shared.global [%0], [%1], 16;"
                 :: "r"(saddr), "l"(gptr) : "memory");
}
__device__ __forceinline__ void cp_commit() {
    asm volatile("cp.async.commit_group;" ::: "memory");
}
template<int N>
__device__ __forceinline__ void cp_wait() {
    asm volatile("cp.async.wait_group %0;" :: "n"(N) : "memory");
}

// fp16: D += A(16x16) * B(16x8), fp32 accumulate
__device__ __forceinline__ void mma168816(float* d, const uint32_t* a, const uint32_t* b) {
    asm volatile(
        "mma.sync.aligned.m16n8k16.row.col.f32.f16.f16.f32 "
        "{%0,%1,%2,%3}, {%4,%5,%6,%7}, {%8,%9}, {%0,%1,%2,%3};"
        : "+f"(d[0]), "+f"(d[1]), "+f"(d[2]), "+f"(d[3])
        : "r"(a[0]), "r"(a[1]), "r"(a[2]), "r"(a[3]), "r"(b[0]), "r"(b[1]));
}

// ldmatrix: 4x / 2x 8x8 b16 matrices from shared
__device__ __forceinline__ void ldsm_x4(uint32_t* r, uint32_t addr) {
    asm volatile("ldmatrix.sync.aligned.m8n8.x4.shared.b16 {%0,%1,%2,%3}, [%4];"
                 : "=r"(r[0]), "=r"(r[1]), "=r"(r[2]), "=r"(r[3]) : "r"(addr));
}
__device__ __forceinline__ void ldsm_x2(uint32_t* r, uint32_t addr) {
    asm volatile("ldmatrix.sync.aligned.m8n8.x2.shared.b16 {%0,%1}, [%2];"
                 : "=r"(r[0]), "=r"(r[1]) : "r"(addr));
}

// =====================================================================
// prep: concat [Wq;Wk] fp32, convert Wv -> fp16
// =====================================================================
__global__ __launch_bounds__(256)
void prep_w_kernel(const float* __restrict__ Wq, const float* __restrict__ Wk,
                   const float* __restrict__ Wv)
{
    const int i = blockIdx.x * blockDim.x + threadIdx.x;
    if (i < 128 * CC)
        g_wqk[i] = (i < II * CC) ? Wq[i] : Wk[i - II * CC];
    if (i < CC * CC)
        g_wvh[i] = __float2half_rn(Wv[i]);
}

// =====================================================================
// prep: transpose x [c][n] fp32 -> xT [n][c] fp16  (64x64 smem tiles)
// =====================================================================
__global__ __launch_bounds__(256)
void prep_xt_kernel(const float* __restrict__ x)
{
    __shared__ float t[64][65];
    const long long bz = blockIdx.z;
    const int n0 = blockIdx.x * 64;
    const int c0 = blockIdx.y * 64;
    const float* src = x + bz * (long long)(CC * NN);
    __half* dst = g_xth + bz * (long long)(NN * CC);

    const int t4 = threadIdx.x & 3;
    const int r  = threadIdx.x >> 2;     // 0..63

    #pragma unroll
    for (int j = 0; j < 4; j++) {
        float4 v = *(const float4*)(src + (long long)(c0 + r) * NN + n0 + t4 * 16 + j * 4);
        t[r][t4 * 16 + j * 4 + 0] = v.x;
        t[r][t4 * 16 + j * 4 + 1] = v.y;
        t[r][t4 * 16 + j * 4 + 2] = v.z;
        t[r][t4 * 16 + j * 4 + 3] = v.w;
    }
    __syncthreads();

    const long long ob = (long long)(n0 + r) * CC + c0 + t4 * 16;
    #pragma unroll
    for (int w = 0; w < 8; w++) {
        __half2 h = __floats2half2_rn(t[t4 * 16 + 2 * w + 0][r],
                                      t[t4 * 16 + 2 * w + 1][r]);
        *(__half2*)(dst + ob + 2 * w) = h;
    }
}

// =====================================================================
// transpose + fp16 split: qk [i][n] fp32 -> qT/kT [n][i] (hi, lo) fp16
// =====================================================================
__global__ __launch_bounds__(256)
void tsplit_kernel()
{
    __shared__ float t[64][65];
    const long long bz = blockIdx.z;
    const int n0 = blockIdx.x * 64;
    const bool isq = (blockIdx.y == 0);
    const float* src = g_qk + bz * (long long)(128 * NN) + (isq ? 0 : (long long)II * NN);
    __half* dh = (isq ? g_qth : g_kth) + bz * (long long)(NN * II);
    __half* dl = (isq ? g_qtl : g_ktl) + bz * (long long)(NN * II);

    const int t4 = threadIdx.x & 3;
    const int r  = threadIdx.x >> 2;     // 0..63

    #pragma unroll
    for (int j = 0; j < 4; j++) {
        float4 v = *(const float4*)(src + (long long)r * NN + n0 + t4 * 16 + j * 4);
        t[r][t4 * 16 + j * 4 + 0] = v.x;
        t[r][t4 * 16 + j * 4 + 1] = v.y;
        t[r][t4 * 16 + j * 4 + 2] = v.z;
        t[r][t4 * 16 + j * 4 + 3] = v.w;
    }
    __syncthreads();

    const long long ob = (long long)(n0 + r) * II + t4 * 16;
    #pragma unroll
    for (int w = 0; w < 8; w++) {
        float v0 = t[t4 * 16 + 2 * w + 0][r];
        float v1 = t[t4 * 16 + 2 * w + 1][r];
        __half h0 = __float2half_rn(v0);
        __half h1 = __float2half_rn(v1);
        __half l0 = __float2half_rn(v0 - __half2float(h0));
        __half l1 = __float2half_rn(v1 - __half2float(h1));
        *(__half2*)(dh + ob + 2 * w) = __halves2half2(h0, h1);
        *(__half2*)(dl + ob + 2 * w) = __halves2half2(l0, l1);
    }
}

// =====================================================================
// S[n,m] = sum_i q[i,n]*k[i,m] via split-fp16 mma (round-10 proven)
// =====================================================================
#define SSTR 36
#define STILE (128 * SSTR)
#define S_SMEM (4 * STILE * 4)

__global__ __launch_bounds__(256, 2)
void s_mma_kernel(const __half* __restrict__ qth, const __half* __restrict__ qtl,
                  const __half* __restrict__ kth, const __half* __restrict__ ktl,
                  float* __restrict__ S)
{
    extern __shared__ uint32_t sw[];
    const int tid = threadIdx.x;
    const long long bz = blockIdx.z;
    qth += bz * (long long)(NN * II);
    qtl += bz * (long long)(NN * II);
    kth += bz * (long long)(NN * II);
    ktl += bz * (long long)(NN * II);
    S   += bz * (long long)NN * NN;

    const int n0 = blockIdx.y * 128;
    const int m0 = blockIdx.x * 128;

    {
        const int lr = tid >> 1;
        const int lsg = tid & 1;
        const uint32_t base = smem_u32(sw);
        const uint32_t sd = base + (uint32_t)(lr * SSTR + lsg * 16) * 4u;
        const long long go = (long long)lr * II + lsg * 32;
        const __half* s0 = qth + (long long)n0 * II + go;
        const __half* s1 = qtl + (long long)n0 * II + go;
        const __half* s2 = kth + (long long)m0 * II + go;
        const __half* s3 = ktl + (long long)m0 * II + go;
        #pragma unroll
        for (int c = 0; c < 4; c++) {
            cp_async16(sd + 0 * STILE * 4 + c * 16, s0 + c * 8);
            cp_async16(sd + 1 * STILE * 4 + c * 16, s1 + c * 8);
            cp_async16(sd + 2 * STILE * 4 + c * 16, s2 + c * 8);
            cp_async16(sd + 3 * STILE * 4 + c * 16, s3 + c * 8);
        }
        cp_commit();
    }
    cp_wait<0>();
    __syncthreads();

    const int wid  = tid >> 5, lane = tid & 31;
    const int wm   = (wid >> 2) * 64;
    const int wn   = (wid & 3) * 32;
    const int g4   = lane >> 2;
    const int tg   = lane & 3;

    float acc[4][4][4];
    #pragma unroll
    for (int i = 0; i < 4; i++)
        #pragma unroll
        for (int j = 0; j < 4; j++)
            #pragma unroll
            for (int r = 0; r < 4; r++) acc[i][j][r] = 0.f;

    const uint32_t* QH = sw;
    const uint32_t* QL = sw + STILE;
    const uint32_t* KH = sw + 2 * STILE;
    const uint32_t* KL = sw + 3 * STILE;

    #pragma unroll
    for (int p = 0; p < 3; p++) {
        const uint32_t* A_ = (p == 2) ? QL : QH;
        const uint32_t* B_ = (p == 1) ? KL : KH;
        #pragma unroll
        for (int s = 0; s < 4; s++) {
            const int kw = s * 8 + tg;
            uint32_t a[4][4], b[4][2];
            #pragma unroll
            for (int mt = 0; mt < 4; mt++) {
                const int r0 = wm + mt * 16 + g4;
                a[mt][0] = A_[r0 * SSTR + kw];
                a[mt][1] = A_[(r0 + 8) * SSTR + kw];
                a[mt][2] = A_[r0 * SSTR + kw + 4];
                a[mt][3] = A_[(r0 + 8) * SSTR + kw + 4];
            }
            #pragma unroll
            for (int nt = 0; nt < 4; nt++) {
                const int nr = wn + nt * 8 + g4;
                b[nt][0] = B_[nr * SSTR + kw];
                b[nt][1] = B_[nr * SSTR + kw + 4];
            }
            #pragma unroll
            for (int mt = 0; mt < 4; mt++)
                #pragma unroll
                for (int nt = 0; nt < 4; nt++)
                    mma168816(acc[mt][nt], a[mt], b[nt]);
        }
    }

    #pragma unroll
    for (int mt = 0; mt < 4; mt++) {
        #pragma unroll
        for (int hf = 0; hf < 2; hf++) {
            const int row = n0 + wm + mt * 16 + g4 + hf * 8;
            const long long rb = (long long)row * NN;
            #pragma unroll
            for (int nt = 0; nt < 4; nt++) {
                const int col = m0 + wn + nt * 8 + 2 * tg;
                float2 o;
                o.x = acc[mt][nt][hf * 2 + 0];
                o.y = acc[mt][nt][hf * 2 + 1];
                *(float2*)(S + rb + col) = o;
            }
        }
    }
}

// =====================================================================
// Generic fp16 NT mma kernel: C[m,n] = sum_k A[m,k]*B[n,k], both fp16
// K-contiguous with row stride LD, K = NCH*64.
// Chunk = 64 halves (128B/row), padded stride 36 words (conflict-free),
// 3-stage ring, ONE barrier + wait per chunk (half the sync rate of the
// previous 32-half chunks). ldmatrix fragments (round-13 proven mapping).
// =====================================================================
#define HSTR 36                      // smem row stride in uint32 (32 payload + 4 pad)
#define HTILE (128 * HSTR)           // words per operand tile (4608)
#define HSTAGE (2 * HTILE)           // A + B per stage (9216 words = 36864 B)
#define H_SMEM (3 * HSTAGE * 4)      // 110592 bytes

template<int LD, int NCH, bool EPI>
__global__ __launch_bounds__(256, 2)
void h_nt_mma_kernel(const __half* __restrict__ A, const __half* __restrict__ Bm,
                     const float* __restrict__ X, void* __restrict__ Out,
                     const float* __restrict__ gamma_p,
                     long long sA, long long sB, long long sO)
{
    extern __shared__ uint32_t smw[];

    const int tid = threadIdx.x;
    const long long bz = blockIdx.z;
    A  += bz * sA;
    Bm += bz * sB;
    const float* Xb = X + bz * sO;
    float*  Of = (float*)Out + bz * sO;
    __half* Oh = (__half*)Out + bz * sO;

    const int m0 = blockIdx.y * 128;
    const int n0 = blockIdx.x * 128;

    // staging: thread t -> row t>>1 (0..127), 64B half (t&1); 4 x 16B per tile
    const int lrow = tid >> 1;
    const int lh   = tid & 1;
    const __half* gA = A  + (long long)(m0 + lrow) * LD + lh * 32;
    const __half* gB = Bm + (long long)(n0 + lrow) * LD + lh * 32;
    const uint32_t sbase = smem_u32(smw);
    const uint32_t sA_st = sbase + (uint32_t)(lrow * HSTR + lh * 16) * 4u;
    const uint32_t sB_st = sA_st + HTILE * 4u;

#define H_ISSUE(c)                                                         \
    do {                                                                   \
        const uint32_t off_ = (uint32_t)((c) % 3) * (HSTAGE * 4u);         \
        const __half* pa_ = gA + (long long)(c) * 64;                      \
        const __half* pb_ = gB + (long long)(c) * 64;                      \
        cp_async16(sA_st + off_,      pa_);                                \
        cp_async16(sA_st + off_ + 16, pa_ + 8);                            \
        cp_async16(sA_st + off_ + 32, pa_ + 16);                           \
        cp_async16(sA_st + off_ + 48, pa_ + 24);                           \
        cp_async16(sB_st + off_,      pb_);                                \
        cp_async16(sB_st + off_ + 16, pb_ + 8);                            \
        cp_async16(sB_st + off_ + 32, pb_ + 16);                           \
        cp_async16(sB_st + off_ + 48, pb_ + 24);                           \
        cp_commit();                                                       \
    } while (0)

    H_ISSUE(0);
    if (NCH > 1) H_ISSUE(1);

    const int wid  = tid >> 5, lane = tid & 31;
    const int wm   = (wid >> 2) * 64;
    const int wn   = (wid & 3) * 32;
    const int g4   = lane >> 2;
    const int tg   = lane & 3;

    // ldmatrix lane addresses (proven mapping, stride now 36 words)
    uint32_t aAddr[4], bAddr[4];
    #pragma unroll
    for (int mt = 0; mt < 4; mt++)
        aAddr[mt] = sbase +
            (uint32_t)((wm + mt * 16 + (lane & 15)) * HSTR + (lane >> 4) * 4) * 4u;
    #pragma unroll
    for (int nt = 0; nt < 4; nt++)
        bAddr[nt] = sbase +
            (uint32_t)(HTILE + (wn + nt * 8 + (lane & 7)) * HSTR + ((lane >> 3) & 1) * 4) * 4u;

    float acc[4][4][4];
    #pragma unroll
    for (int i = 0; i < 4; i++)
        #pragma unroll
        for (int j = 0; j < 4; j++)
            #pragma unroll
            for (int r = 0; r < 4; r++) acc[i][j][r] = 0.f;

    for (int c = 0; c < NCH; c++) {
        if (c + 1 < NCH) cp_wait<1>();
        else             cp_wait<0>();
        __syncthreads();                       // all warps done with buf (c-1)%3

        if (c + 2 < NCH) H_ISSUE(c + 2);       // fills buf (c+2)%3 == (c-1)%3

        const uint32_t so = (uint32_t)(c % 3) * (HSTAGE * 4u);

        #pragma unroll
        for (int s = 0; s < 4; s++) {          // four k16 steps per 64-chunk
            const uint32_t ko = so + (uint32_t)s * 32u;   // s*8 words
            uint32_t a[4][4], b[4][2];
            #pragma unroll
            for (int mt = 0; mt < 4; mt++)
                ldsm_x4(a[mt], aAddr[mt] + ko);
            #pragma unroll
            for (int nt = 0; nt < 4; nt++)
                ldsm_x2(b[nt], bAddr[nt] + ko);
            #pragma unroll
            for (int mt = 0; mt < 4; mt++)
                #pragma unroll
                for (int nt = 0; nt < 4; nt++)
                    mma168816(acc[mt][nt], a[mt], b[nt]);
        }
    }

    if (EPI) {
        const float g = *gamma_p;
        #pragma unroll
        for (int mt = 0; mt < 4; mt++) {
            #pragma unroll
            for (int hf = 0; hf < 2; hf++) {
                const int m = m0 + wm + mt * 16 + g4 + hf * 8;
                const long long rb = (long long)m * NN;
                #pragma unroll
                for (int nt = 0; nt < 4; nt++) {
                    const int n = n0 + wn + nt * 8 + 2 * tg;
                    float2 xr = *(const float2*)(Xb + rb + n);
                    float2 o;
                    o.x = fmaf(g, acc[mt][nt][hf * 2 + 0], xr.x);
                    o.y = fmaf(g, acc[mt][nt][hf * 2 + 1], xr.y);
                    *(float2*)(Of + rb + n) = o;
                }
            }
        }
    } else {
        #pragma unroll
        for (int mt = 0; mt < 4; mt++) {
            #pragma unroll
            for (int hf = 0; hf < 2; hf++) {
                const int m = m0 + wm + mt * 16 + g4 + hf * 8;
                const long long rb = (long long)m * NN;
                #pragma unroll
                for (int nt = 0; nt < 4; nt++) {
                    const int n = n0 + wn + nt * 8 + 2 * tg;
                    __half2 h = __floats2half2_rn(acc[mt][nt][hf * 2 + 0],
                                                  acc[mt][nt][hf * 2 + 1]);
                    *(__half2*)(Oh + rb + n) = h;
                }
            }
        }
    }
#undef H_ISSUE
}

// ---------------- generic tiled SGEMM (fp32 SIMT, qk producer) ----------------
static const int TM = 128, TN = 128, TK = 16;

template<bool AK, bool BK, bool EPI>
__global__ __launch_bounds__(256, 2)
void gemm_k(const float* __restrict__ A, const float* __restrict__ Bm,
            float* __restrict__ Cm, int M, int N, int K,
            long long sA, long long sB, long long sC,
            const float* __restrict__ R, long long sR,
            const float* __restrict__ gamma_p)
{
    A  += sA * (long long)blockIdx.z;
    Bm += sB * (long long)blockIdx.z;
    Cm += sC * (long long)blockIdx.z;
    if (EPI) R += sR * (long long)blockIdx.z;

    __shared__ float As[TK][TM];
    __shared__ float Bs[TK][TN];

    const int tid = threadIdx.x;
    const int n0 = blockIdx.x * TN;
    const int m0 = blockIdx.y * TM;
    const int tx = tid & 15;
    const int ty = tid >> 4;

    float acc[8][8];
    #pragma unroll
    for (int i = 0; i < 8; i++)
        #pragma unroll
        for (int j = 0; j < 8; j++) acc[i][j] = 0.f;

    for (int k0 = 0; k0 < K; k0 += TK) {
        if (AK) {
            const int row = tid >> 1;
            const int kc  = (tid & 1) * 8;
            const int m   = m0 + row;
            float4 v0 = make_float4(0.f, 0.f, 0.f, 0.f), v1 = v0;
            if (m < M) {
                const float* p = A + (long long)m * K + k0 + kc;
                v0 = *(const float4*)p;
                v1 = *(const float4*)(p + 4);
            }
            As[kc + 0][row] = v0.x; As[kc + 1][row] = v0.y;
            As[kc + 2][row] = v0.z; As[kc + 3][row] = v0.w;
            As[kc + 4][row] = v1.x; As[kc + 5][row] = v1.y;
            As[kc + 6][row] = v1.z; As[kc + 7][row] = v1.w;
        } else {
            const int kr = tid >> 4;
            const int mc = (tid & 15) * 8;
            const float* p = A + (long long)(k0 + kr) * M + m0 + mc;
            *(float4*)&As[kr][mc]     = *(const float4*)p;
            *(float4*)&As[kr][mc + 4] = *(const float4*)(p + 4);
        }
        if (!BK) {
            const int kr = tid >> 4;
            const int nc = (tid & 15) * 8;
            const float* p = Bm + (long long)(k0 + kr) * N + n0 + nc;
            *(float4*)&Bs[kr][nc]     = *(const float4*)p;
            *(float4*)&Bs[kr][nc + 4] = *(const float4*)(p + 4);
        } else {
            const int row = tid >> 1;
            const int kc  = (tid & 1) * 8;
            const float* p = Bm + (long long)(n0 + row) * K + k0 + kc;
            float4 v0 = *(const float4*)p;
            float4 v1 = *(const float4*)(p + 4);
            Bs[kc + 0][row] = v0.x; Bs[kc + 1][row] = v0.y;
            Bs[kc + 2][row] = v0.z; Bs[kc + 3][row] = v0.w;
            Bs[kc + 4][row] = v1.x; Bs[kc + 5][row] = v1.y;
            Bs[kc + 6][row] = v1.z; Bs[kc + 7][row] = v1.w;
        }
        __syncthreads();

        #pragma unroll
        for (int kk = 0; kk < TK; kk++) {
            float a[8], b[8];
            *(float4*)(a)     = *(const float4*)&As[kk][ty * 8];
            *(float4*)(a + 4) = *(const float4*)&As[kk][ty * 8 + 4];
            *(float4*)(b)     = *(const float4*)&Bs[kk][tx * 8];
            *(float4*)(b + 4) = *(const float4*)&Bs[kk][tx * 8 + 4];
            #pragma unroll
            for (int i = 0; i < 8; i++)
                #pragma unroll
                for (int j = 0; j < 8; j++)
                    acc[i][j] = fmaf(a[i], b[j], acc[i][j]);
        }
        __syncthreads();
    }

    const float g = EPI ? *gamma_p : 0.f;
    #pragma unroll
    for (int i = 0; i < 8; i++) {
        const int m = m0 + ty * 8 + i;
        if (m < M) {
            float* dst = Cm + (long long)m * N + n0 + tx * 8;
            if (EPI) {
                const float* r = R + (long long)m * N + n0 + tx * 8;
                float4 r0 = *(const float4*)r;
                float4 r1 = *(const float4*)(r + 4);
                float4 o0, o1;
                o0.x = fmaf(g, acc[i][0], r0.x); o0.y = fmaf(g, acc[i][1], r0.y);
                o0.z = fmaf(g, acc[i][2], r0.z); o0.w = fmaf(g, acc[i][3], r0.w);
                o1.x = fmaf(g, acc[i][4], r1.x); o1.y = fmaf(g, acc[i][5], r1.y);
                o1.z = fmaf(g, acc[i][6], r1.z); o1.w = fmaf(g, acc[i][7], r1.w);
                *(float4*)dst       = o0;
                *(float4*)(dst + 4) = o1;
            } else {
                float4 o0 = make_float4(acc[i][0], acc[i][1], acc[i][2], acc[i][3]);
                float4 o1 = make_float4(acc[i][4], acc[i][5], acc[i][6], acc[i][7]);
                *(float4*)dst       = o0;
                *(float4*)(dst + 4) = o1;
            }
        }
    }
}

// ---------------- row softmax; reads fp32 S, writes fp16 P ----------------
__global__ __launch_bounds__(256)
void softmax_rows(const float* __restrict__ S, __half* __restrict__ P)
{
    __shared__ float red[8];
    const float* p = S + (size_t)blockIdx.x * NN;
    __half*      o = P + (size_t)blockIdx.x * NN;
    const int tid  = threadIdx.x;
    const int lane = tid & 31;
    const int wid  = tid >> 5;

    float v[9];
    float m = -1e30f;
    #pragma unroll
    for (int j = 0; j < 9; j++) {
        v[j] = p[tid + 256 * j];
        m = fmaxf(m, v[j]);
    }
    #pragma unroll
    for (int ofs = 16; ofs; ofs >>= 1) m = fmaxf(m, __shfl_xor_sync(0xffffffffu, m, ofs));
    if (lane == 0) red[wid] = m;
    __syncthreads();
    m = red[0];
    #pragma unroll
    for (int i = 1; i < 8; i++) m = fmaxf(m, red[i]);
    __syncthreads();

    float s = 0.f;
    #pragma unroll
    for (int j = 0; j < 9; j++) {
        v[j] = expf(v[j] - m);
        s += v[j];
    }
    #pragma unroll
    for (int ofs = 16; ofs; ofs >>= 1) s += __shfl_xor_sync(0xffffffffu, s, ofs);
    if (lane == 0) red[wid] = s;
    __syncthreads();
    s = 0.f;
    #pragma unroll
    for (int i = 0; i < 8; i++) s += red[i];

    const float inv = 1.f / s;
    #pragma unroll
    for (int j = 0; j < 9; j++)
        o[tid + 256 * j] = __float2half_rn(v[j] * inv);
}

// ---------------- launch ----------------
extern "C" void kernel_launch(void* const* d_in, const int* in_sizes, int n_in,
                              void* d_out, int out_size)
{
    const float* x     = (const float*)d_in[0];   // (16,512,48,48)
    const float* Wq    = (const float*)d_in[1];   // (64,512)
    const float* Wk    = (const float*)d_in[2];   // (64,512)
    const float* Wv    = (const float*)d_in[3];   // (512,512)
    const float* gamma = (const float*)d_in[4];   // (1,)
    float* out = (float*)d_out;

    float *qk, *s, *wqk;
    __half *ph, *vh, *qth, *qtl, *kth, *ktl, *xth, *wvh;
    cudaGetSymbolAddress((void**)&qk,  g_qk);
    cudaGetSymbolAddress((void**)&s,   g_s);
    cudaGetSymbolAddress((void**)&wqk, g_wqk);
    cudaGetSymbolAddress((void**)&ph,  g_ph);
    cudaGetSymbolAddress((void**)&vh,  g_vh);
    cudaGetSymbolAddress((void**)&qth, g_qth);
    cudaGetSymbolAddress((void**)&qtl, g_qtl);
    cudaGetSymbolAddress((void**)&kth, g_kth);
    cudaGetSymbolAddress((void**)&ktl, g_ktl);
    cudaGetSymbolAddress((void**)&xth, g_xth);
    cudaGetSymbolAddress((void**)&wvh, g_wvh);

    const long long sX = (long long)CC * NN;

    dim3 blk(256);

    // prep: [Wq;Wk] concat, Wv->fp16; x -> xT fp16
    prep_w_kernel<<<(CC * CC + 255) / 256, 256>>>(Wq, Wk, Wv);
    prep_xt_kernel<<<dim3(NN / 64, CC / 64, BB), blk>>>(x);

    // [q; k] = [Wq; Wk] @ x : one fused fp32 SIMT launch, M=128
    gemm_k<true, false, false><<<dim3(NN / TN, 1, BB), blk>>>(
        wqk, x, qk, 128, NN, CC, 0, sX, (long long)128 * NN, nullptr, 0, nullptr);

    // v = Wv @ xT : fp16 mma (64-chunk, 3-stage)
    cudaFuncSetAttribute(h_nt_mma_kernel<CC, CC / 64, false>,
                         cudaFuncAttributeMaxDynamicSharedMemorySize, H_SMEM);
    h_nt_mma_kernel<CC, CC / 64, false><<<dim3(NN / 128, CC / 128, BB), blk, H_SMEM>>>(
        wvh, xth, nullptr, vh, nullptr, 0, (long long)NN * CC, sX);

    // transpose + fp16 split of q, k
    tsplit_kernel<<<dim3(NN / 64, 2, BB), blk>>>();

    // S = q^T @ k  (split-fp16 mma, fp32-grade accuracy)
    cudaFuncSetAttribute(s_mma_kernel,
                         cudaFuncAttributeMaxDynamicSharedMemorySize, S_SMEM);
    s_mma_kernel<<<dim3(NN / 128, NN / 128, BB), blk, S_SMEM>>>(
        qth, qtl, kth, ktl, s);

    // P = softmax(S), emitted fp16
    softmax_rows<<<BB * NN, 256>>>(s, ph);

    // out = gamma * (V @ P^T) + x  (fp16 mma, 64-chunk, 3-stage)
    cudaFuncSetAttribute(h_nt_mma_kernel<NN, NN / 64, true>,
                         cudaFuncAttributeMaxDynamicSharedMemorySize, H_SMEM);
    h_nt_mma_kernel<NN, NN / 64, true><<<dim3(NN / 128, CC / 128, BB), blk, H_SMEM>>>(
        vh, ph, x, out, gamma, sX, (long long)NN * NN, sX);
}

// round 15
// speedup vs baseline: 1.0609x; 1.0609x over previous
#include <cuda_runtime.h>
#include <cuda_fp16.h>
#include <stdint.h>
#include <math.h>

// Problem constants
#define BB 16
#define CC 512
#define NN 2304      // 48*48
#define II 64

// ---------------- scratch (static device globals; no allocation) ----------------
__device__ __half g_qth[(size_t)BB * NN * II];        // 4.7 MB qT hi [n][i]
__device__ __half g_qtl[(size_t)BB * NN * II];        // 4.7 MB qT lo
__device__ __half g_kth[(size_t)BB * NN * II];        // 4.7 MB kT hi [m][i]
__device__ __half g_ktl[(size_t)BB * NN * II];        // 4.7 MB kT lo
__device__ float  g_s[(size_t)BB * NN * NN];          // 324 MB fp32 logits S
__device__ __half g_ph[(size_t)BB * NN * NN];         // 162 MB fp16 softmax P
__device__ __half g_vh[(size_t)BB * CC * NN];         //  36 MB fp16 V
__device__ __half g_xth[(size_t)BB * NN * CC];        //  74 MB fp16 xT [n][c]
__device__ float  g_wqk[128 * CC];                    // [Wq; Wk] concat fp32
__device__ __half g_wvh[CC * CC];                     // Wv fp16

// =====================================================================
// helpers
// =====================================================================
__device__ __forceinline__ uint32_t smem_u32(const void* p) {
    uint32_t a;
    asm("{ .reg .u64 t; cvta.to.shared.u64 t, %1; cvt.u32.u64 %0, t; }"
        : "=r"(a) : "l"(p));
    return a;
}

__device__ __forceinline__ void cp_async16(uint32_t saddr, const void* gptr) {
    asm volatile("cp.async.cg.shared.global [%0], [%1], 16;"
                 :: "r"(saddr), "l"(gptr) : "memory");
}
__device__ __forceinline__ void cp_commit() {
    asm volatile("cp.async.commit_group;" ::: "memory");
}
template<int N>
__device__ __forceinline__ void cp_wait() {
    asm volatile("cp.async.wait_group %0;" :: "n"(N) : "memory");
}

// fp16: D += A(16x16) * B(16x8), fp32 accumulate
__device__ __forceinline__ void mma168816(float* d, const uint32_t* a, const uint32_t* b) {
    asm volatile(
        "mma.sync.aligned.m16n8k16.row.col.f32.f16.f16.f32 "
        "{%0,%1,%2,%3}, {%4,%5,%6,%7}, {%8,%9}, {%0,%1,%2,%3};"
        : "+f"(d[0]), "+f"(d[1]), "+f"(d[2]), "+f"(d[3])
        : "r"(a[0]), "r"(a[1]), "r"(a[2]), "r"(a[3]), "r"(b[0]), "r"(b[1]));
}

// ldmatrix: 4x / 2x 8x8 b16 matrices from shared
__device__ __forceinline__ void ldsm_x4(uint32_t* r, uint32_t addr) {
    asm volatile("ldmatrix.sync.aligned.m8n8.x4.shared.b16 {%0,%1,%2,%3}, [%4];"
                 : "=r"(r[0]), "=r"(r[1]), "=r"(r[2]), "=r"(r[3]) : "r"(addr));
}
__device__ __forceinline__ void ldsm_x2(uint32_t* r, uint32_t addr) {
    asm volatile("ldmatrix.sync.aligned.m8n8.x2.shared.b16 {%0,%1}, [%2];"
                 : "=r"(r[0]), "=r"(r[1]) : "r"(addr));
}

// =====================================================================
// prep: concat [Wq;Wk] fp32, convert Wv -> fp16
// =====================================================================
__global__ __launch_bounds__(256)
void prep_w_kernel(const float* __restrict__ Wq, const float* __restrict__ Wk,
                   const float* __restrict__ Wv)
{
    const int i = blockIdx.x * blockDim.x + threadIdx.x;
    if (i < 128 * CC)
        g_wqk[i] = (i < II * CC) ? Wq[i] : Wk[i - II * CC];
    if (i < CC * CC)
        g_wvh[i] = __float2half_rn(Wv[i]);
}

// =====================================================================
// prep: transpose x [c][n] fp32 -> xT [n][c] fp16  (64x64 smem tiles)
// =====================================================================
__global__ __launch_bounds__(256)
void prep_xt_kernel(const float* __restrict__ x)
{
    __shared__ float t[64][65];
    const long long bz = blockIdx.z;
    const int n0 = blockIdx.x * 64;
    const int c0 = blockIdx.y * 64;
    const float* src = x + bz * (long long)(CC * NN);
    __half* dst = g_xth + bz * (long long)(NN * CC);

    const int t4 = threadIdx.x & 3;
    const int r  = threadIdx.x >> 2;     // 0..63

    #pragma unroll
    for (int j = 0; j < 4; j++) {
        float4 v = *(const float4*)(src + (long long)(c0 + r) * NN + n0 + t4 * 16 + j * 4);
        t[r][t4 * 16 + j * 4 + 0] = v.x;
        t[r][t4 * 16 + j * 4 + 1] = v.y;
        t[r][t4 * 16 + j * 4 + 2] = v.z;
        t[r][t4 * 16 + j * 4 + 3] = v.w;
    }
    __syncthreads();

    const long long ob = (long long)(n0 + r) * CC + c0 + t4 * 16;
    #pragma unroll
    for (int w = 0; w < 8; w++) {
        __half2 h = __floats2half2_rn(t[t4 * 16 + 2 * w + 0][r],
                                      t[t4 * 16 + 2 * w + 1][r]);
        *(__half2*)(dst + ob + 2 * w) = h;
    }
}

// =====================================================================
// qk GEMM (fp32 SIMT) with FUSED transpose + fp16 split epilogue.
// [q;k](i,n) = sum_c Wqk[i,c] * x[c,n];  i in 0..127 (q:0-63, k:64-127)
// Epilogue emits qT/kT [n][i] hi/lo fp16 directly from fp32 acc —
// bit-identical to the old gemm_k + tsplit pair, no fp32 round trip.
// grid (NN/128, 1, BB), block 256
// =====================================================================
__global__ __launch_bounds__(256, 2)
void qk_gemm_kernel(const float* __restrict__ x)
{
    __shared__ float As[16][128];
    __shared__ float Bs[16][128];

    const int tid = threadIdx.x;
    const long long bz = blockIdx.z;
    const float* Bm = x + bz * (long long)(CC * NN);
    const int n0 = blockIdx.x * 128;
    const int tx = tid & 15;
    const int ty = tid >> 4;

    float acc[8][8];
    #pragma unroll
    for (int i = 0; i < 8; i++)
        #pragma unroll
        for (int j = 0; j < 8; j++) acc[i][j] = 0.f;

    for (int k0 = 0; k0 < CC; k0 += 16) {
        // A = g_wqk, row-major 128 x 512 (k contiguous)
        {
            const int row = tid >> 1;
            const int kc  = (tid & 1) * 8;
            const float* p = g_wqk + (long long)row * CC + k0 + kc;
            float4 v0 = *(const float4*)p;
            float4 v1 = *(const float4*)(p + 4);
            As[kc + 0][row] = v0.x; As[kc + 1][row] = v0.y;
            As[kc + 2][row] = v0.z; As[kc + 3][row] = v0.w;
            As[kc + 4][row] = v1.x; As[kc + 5][row] = v1.y;
            As[kc + 6][row] = v1.z; As[kc + 7][row] = v1.w;
        }
        // B = x, K x N (n contiguous)
        {
            const int kr = tid >> 4;
            const int nc = (tid & 15) * 8;
            const float* p = Bm + (long long)(k0 + kr) * NN + n0 + nc;
            *(float4*)&Bs[kr][nc]     = *(const float4*)p;
            *(float4*)&Bs[kr][nc + 4] = *(const float4*)(p + 4);
        }
        __syncthreads();

        #pragma unroll
        for (int kk = 0; kk < 16; kk++) {
            float a[8], b[8];
            *(float4*)(a)     = *(const float4*)&As[kk][ty * 8];
            *(float4*)(a + 4) = *(const float4*)&As[kk][ty * 8 + 4];
            *(float4*)(b)     = *(const float4*)&Bs[kk][tx * 8];
            *(float4*)(b + 4) = *(const float4*)&Bs[kk][tx * 8 + 4];
            #pragma unroll
            for (int i = 0; i < 8; i++)
                #pragma unroll
                for (int j = 0; j < 8; j++)
                    acc[i][j] = fmaf(a[i], b[j], acc[i][j]);
        }
        __syncthreads();
    }

    // ---- fused epilogue: transposed hi/lo split store ----
    // thread rows i = ty*8..ty*8+7 (all within q half if ty<8, else k half)
    const bool isq = (ty < 8);
    const int ib = (ty * 8) & 63;                  // i offset within q/k half
    __half* dh = (isq ? g_qth : g_kth) + bz * (long long)(NN * II);
    __half* dl = (isq ? g_qtl : g_ktl) + bz * (long long)(NN * II);

    #pragma unroll
    for (int j = 0; j < 8; j++) {
        const int n = n0 + tx * 8 + j;
        alignas(16) __half2 H[4];
        alignas(16) __half2 L[4];
        #pragma unroll
        for (int p = 0; p < 4; p++) {
            float v0 = acc[2 * p + 0][j];
            float v1 = acc[2 * p + 1][j];
            __half h0 = __float2half_rn(v0);
            __half h1 = __float2half_rn(v1);
            __half l0 = __float2half_rn(v0 - __half2float(h0));
            __half l1 = __float2half_rn(v1 - __half2float(h1));
            H[p] = __halves2half2(h0, h1);
            L[p] = __halves2half2(l0, l1);
        }
        *(float4*)(dh + (long long)n * II + ib) = *(const float4*)H;
        *(float4*)(dl + (long long)n * II + ib) = *(const float4*)L;
    }
}

// =====================================================================
// S[n,m] = sum_i q[i,n]*k[i,m] via split-fp16 mma (round-10 proven)
// =====================================================================
#define SSTR 36
#define STILE (128 * SSTR)
#define S_SMEM (4 * STILE * 4)

__global__ __launch_bounds__(256, 2)
void s_mma_kernel(const __half* __restrict__ qth, const __half* __restrict__ qtl,
                  const __half* __restrict__ kth, const __half* __restrict__ ktl,
                  float* __restrict__ S)
{
    extern __shared__ uint32_t sw[];
    const int tid = threadIdx.x;
    const long long bz = blockIdx.z;
    qth += bz * (long long)(NN * II);
    qtl += bz * (long long)(NN * II);
    kth += bz * (long long)(NN * II);
    ktl += bz * (long long)(NN * II);
    S   += bz * (long long)NN * NN;

    const int n0 = blockIdx.y * 128;
    const int m0 = blockIdx.x * 128;

    {
        const int lr = tid >> 1;
        const int lsg = tid & 1;
        const uint32_t base = smem_u32(sw);
        const uint32_t sd = base + (uint32_t)(lr * SSTR + lsg * 16) * 4u;
        const long long go = (long long)lr * II + lsg * 32;
        const __half* s0 = qth + (long long)n0 * II + go;
        const __half* s1 = qtl + (long long)n0 * II + go;
        const __half* s2 = kth + (long long)m0 * II + go;
        const __half* s3 = ktl + (long long)m0 * II + go;
        #pragma unroll
        for (int c = 0; c < 4; c++) {
            cp_async16(sd + 0 * STILE * 4 + c * 16, s0 + c * 8);
            cp_async16(sd + 1 * STILE * 4 + c * 16, s1 + c * 8);
            cp_async16(sd + 2 * STILE * 4 + c * 16, s2 + c * 8);
            cp_async16(sd + 3 * STILE * 4 + c * 16, s3 + c * 8);
        }
        cp_commit();
    }
    cp_wait<0>();
    __syncthreads();

    const int wid  = tid >> 5, lane = tid & 31;
    const int wm   = (wid >> 2) * 64;
    const int wn   = (wid & 3) * 32;
    const int g4   = lane >> 2;
    const int tg   = lane & 3;

    float acc[4][4][4];
    #pragma unroll
    for (int i = 0; i < 4; i++)
        #pragma unroll
        for (int j = 0; j < 4; j++)
            #pragma unroll
            for (int r = 0; r < 4; r++) acc[i][j][r] = 0.f;

    const uint32_t* QH = sw;
    const uint32_t* QL = sw + STILE;
    const uint32_t* KH = sw + 2 * STILE;
    const uint32_t* KL = sw + 3 * STILE;

    #pragma unroll
    for (int p = 0; p < 3; p++) {
        const uint32_t* A_ = (p == 2) ? QL : QH;
        const uint32_t* B_ = (p == 1) ? KL : KH;
        #pragma unroll
        for (int s = 0; s < 4; s++) {
            const int kw = s * 8 + tg;
            uint32_t a[4][4], b[4][2];
            #pragma unroll
            for (int mt = 0; mt < 4; mt++) {
                const int r0 = wm + mt * 16 + g4;
                a[mt][0] = A_[r0 * SSTR + kw];
                a[mt][1] = A_[(r0 + 8) * SSTR + kw];
                a[mt][2] = A_[r0 * SSTR + kw + 4];
                a[mt][3] = A_[(r0 + 8) * SSTR + kw + 4];
            }
            #pragma unroll
            for (int nt = 0; nt < 4; nt++) {
                const int nr = wn + nt * 8 + g4;
                b[nt][0] = B_[nr * SSTR + kw];
                b[nt][1] = B_[nr * SSTR + kw + 4];
            }
            #pragma unroll
            for (int mt = 0; mt < 4; mt++)
                #pragma unroll
                for (int nt = 0; nt < 4; nt++)
                    mma168816(acc[mt][nt], a[mt], b[nt]);
        }
    }

    #pragma unroll
    for (int mt = 0; mt < 4; mt++) {
        #pragma unroll
        for (int hf = 0; hf < 2; hf++) {
            const int row = n0 + wm + mt * 16 + g4 + hf * 8;
            const long long rb = (long long)row * NN;
            #pragma unroll
            for (int nt = 0; nt < 4; nt++) {
                const int col = m0 + wn + nt * 8 + 2 * tg;
                float2 o;
                o.x = acc[mt][nt][hf * 2 + 0];
                o.y = acc[mt][nt][hf * 2 + 1];
                *(float2*)(S + rb + col) = o;
            }
        }
    }
}

// =====================================================================
// Generic fp16 NT mma kernel (round-13 proven EXACTLY: 32-chunk, 4-stage,
// ldmatrix fragments, HSTR 20).
// =====================================================================
#define HSTR 20
#define HTILE (128 * HSTR)
#define HSTAGE (2 * HTILE)
#define H_SMEM (4 * HSTAGE * 4)

template<int LD, int NCH, bool EPI>
__global__ __launch_bounds__(256, 2)
void h_nt_mma_kernel(const __half* __restrict__ A, const __half* __restrict__ Bm,
                     const float* __restrict__ X, void* __restrict__ Out,
                     const float* __restrict__ gamma_p,
                     long long sA, long long sB, long long sO)
{
    extern __shared__ uint32_t smw[];

    const int tid = threadIdx.x;
    const long long bz = blockIdx.z;
    A  += bz * sA;
    Bm += bz * sB;
    const float* Xb = X + bz * sO;
    float*  Of = (float*)Out + bz * sO;
    __half* Oh = (__half*)Out + bz * sO;

    const int m0 = blockIdx.y * 128;
    const int n0 = blockIdx.x * 128;

    const int lrow = tid >> 1;
    const int lh   = tid & 1;
    const __half* gA = A  + (long long)(m0 + lrow) * LD + lh * 16;
    const __half* gB = Bm + (long long)(n0 + lrow) * LD + lh * 16;
    const uint32_t sbase = smem_u32(smw);
    const uint32_t sA_st = sbase + (uint32_t)(lrow * HSTR + lh * 8) * 4u;
    const uint32_t sB_st = sA_st + HTILE * 4u;

#define H_ISSUE(c)                                                         \
    do {                                                                   \
        const uint32_t off_ = (uint32_t)((c) & 3) * (HSTAGE * 4u);         \
        const __half* pa_ = gA + (c) * 32;                                 \
        const __half* pb_ = gB + (c) * 32;                                 \
        cp_async16(sA_st + off_,      pa_);                                \
        cp_async16(sA_st + off_ + 16, pa_ + 8);                            \
        cp_async16(sB_st + off_,      pb_);                                \
        cp_async16(sB_st + off_ + 16, pb_ + 8);                            \
        cp_commit();                                                       \
    } while (0)

    H_ISSUE(0); H_ISSUE(1); H_ISSUE(2);

    const int wid  = tid >> 5, lane = tid & 31;
    const int wm   = (wid >> 2) * 64;
    const int wn   = (wid & 3) * 32;
    const int g4   = lane >> 2;
    const int tg   = lane & 3;

    uint32_t aAddr[4], bAddr[4];
    #pragma unroll
    for (int mt = 0; mt < 4; mt++)
        aAddr[mt] = sbase +
            (uint32_t)((wm + mt * 16 + (lane & 15)) * HSTR + (lane >> 4) * 4) * 4u;
    #pragma unroll
    for (int nt = 0; nt < 4; nt++)
        bAddr[nt] = sbase +
            (uint32_t)(HTILE + (wn + nt * 8 + (lane & 7)) * HSTR + ((lane >> 3) & 1) * 4) * 4u;

    float acc[4][4][4];
    #pragma unroll
    for (int i = 0; i < 4; i++)
        #pragma unroll
        for (int j = 0; j < 4; j++)
            #pragma unroll
            for (int r = 0; r < 4; r++) acc[i][j][r] = 0.f;

    for (int c = 0; c < NCH; c++) {
        if (c + 2 < NCH)       cp_wait<2>();
        else if (c + 1 < NCH)  cp_wait<1>();
        else                   cp_wait<0>();
        __syncthreads();

        if (c + 3 < NCH) H_ISSUE(c + 3);

        const uint32_t so = (uint32_t)(c & 3) * (HSTAGE * 4u);

        #pragma unroll
        for (int s = 0; s < 2; s++) {
            const uint32_t ko = so + (uint32_t)s * 32u;
            uint32_t a[4][4], b[4][2];
            #pragma unroll
            for (int mt = 0; mt < 4; mt++)
                ldsm_x4(a[mt], aAddr[mt] + ko);
            #pragma unroll
            for (int nt = 0; nt < 4; nt++)
                ldsm_x2(b[nt], bAddr[nt] + ko);
            #pragma unroll
            for (int mt = 0; mt < 4; mt++)
                #pragma unroll
                for (int nt = 0; nt < 4; nt++)
                    mma168816(acc[mt][nt], a[mt], b[nt]);
        }
    }

    if (EPI) {
        const float g = *gamma_p;
        #pragma unroll
        for (int mt = 0; mt < 4; mt++) {
            #pragma unroll
            for (int hf = 0; hf < 2; hf++) {
                const int m = m0 + wm + mt * 16 + g4 + hf * 8;
                const long long rb = (long long)m * NN;
                #pragma unroll
                for (int nt = 0; nt < 4; nt++) {
                    const int n = n0 + wn + nt * 8 + 2 * tg;
                    float2 xr = *(const float2*)(Xb + rb + n);
                    float2 o;
                    o.x = fmaf(g, acc[mt][nt][hf * 2 + 0], xr.x);
                    o.y = fmaf(g, acc[mt][nt][hf * 2 + 1], xr.y);
                    *(float2*)(Of + rb + n) = o;
                }
            }
        }
    } else {
        #pragma unroll
        for (int mt = 0; mt < 4; mt++) {
            #pragma unroll
            for (int hf = 0; hf < 2; hf++) {
                const int m = m0 + wm + mt * 16 + g4 + hf * 8;
                const long long rb = (long long)m * NN;
                #pragma unroll
                for (int nt = 0; nt < 4; nt++) {
                    const int n = n0 + wn + nt * 8 + 2 * tg;
                    __half2 h = __floats2half2_rn(acc[mt][nt][hf * 2 + 0],
                                                  acc[mt][nt][hf * 2 + 1]);
                    *(__half2*)(Oh + rb + n) = h;
                }
            }
        }
    }
#undef H_ISSUE
}

// ---------------- row softmax: 6 rows per block (fewer waves) ----------------
#define SMR 6

__global__ __launch_bounds__(256)
void softmax_rows(const float* __restrict__ S, __half* __restrict__ P)
{
    __shared__ float red[8];
    const size_t r0 = (size_t)blockIdx.x * SMR;
    const int tid  = threadIdx.x;
    const int lane = tid & 31;
    const int wid  = tid >> 5;

    for (int r = 0; r < SMR; r++) {
        const float* p = S + (r0 + r) * NN;
        __half*      o = P + (r0 + r) * NN;

        float v[9];
        float m = -1e30f;
        #pragma unroll
        for (int j = 0; j < 9; j++) {
            v[j] = p[tid + 256 * j];
            m = fmaxf(m, v[j]);
        }
        #pragma unroll
        for (int ofs = 16; ofs; ofs >>= 1) m = fmaxf(m, __shfl_xor_sync(0xffffffffu, m, ofs));
        if (lane == 0) red[wid] = m;
        __syncthreads();
        m = red[0];
        #pragma unroll
        for (int i = 1; i < 8; i++) m = fmaxf(m, red[i]);
        __syncthreads();

        float s = 0.f;
        #pragma unroll
        for (int j = 0; j < 9; j++) {
            v[j] = expf(v[j] - m);
            s += v[j];
        }
        #pragma unroll
        for (int ofs = 16; ofs; ofs >>= 1) s += __shfl_xor_sync(0xffffffffu, s, ofs);
        if (lane == 0) red[wid] = s;
        __syncthreads();
        s = 0.f;
        #pragma unroll
        for (int i = 0; i < 8; i++) s += red[i];

        const float inv = 1.f / s;
        #pragma unroll
        for (int j = 0; j < 9; j++)
            o[tid + 256 * j] = __float2half_rn(v[j] * inv);
        __syncthreads();   // red[] reuse hazard between rows
    }
}

// ---------------- launch ----------------
extern "C" void kernel_launch(void* const* d_in, const int* in_sizes, int n_in,
                              void* d_out, int out_size)
{
    const float* x     = (const float*)d_in[0];   // (16,512,48,48)
    const float* Wq    = (const float*)d_in[1];   // (64,512)
    const float* Wk    = (const float*)d_in[2];   // (64,512)
    const float* Wv    = (const float*)d_in[3];   // (512,512)
    const float* gamma = (const float*)d_in[4];   // (1,)
    float* out = (float*)d_out;

    float *s;
    __half *ph, *vh, *qth, *qtl, *kth, *ktl, *xth, *wvh;
    cudaGetSymbolAddress((void**)&s,   g_s);
    cudaGetSymbolAddress((void**)&ph,  g_ph);
    cudaGetSymbolAddress((void**)&vh,  g_vh);
    cudaGetSymbolAddress((void**)&qth, g_qth);
    cudaGetSymbolAddress((void**)&qtl, g_qtl);
    cudaGetSymbolAddress((void**)&kth, g_kth);
    cudaGetSymbolAddress((void**)&ktl, g_ktl);
    cudaGetSymbolAddress((void**)&xth, g_xth);
    cudaGetSymbolAddress((void**)&wvh, g_wvh);

    const long long sX = (long long)CC * NN;

    dim3 blk(256);

    // prep: [Wq;Wk] concat, Wv->fp16; x -> xT fp16
    prep_w_kernel<<<(CC * CC + 255) / 256, 256>>>(Wq, Wk, Wv);
    prep_xt_kernel<<<dim3(NN / 64, CC / 64, BB), blk>>>(x);

    // [q;k] GEMM with fused transpose + hi/lo split epilogue
    qk_gemm_kernel<<<dim3(NN / 128, 1, BB), blk>>>(x);

    // v = Wv @ xT : fp16 mma (round-13 proven config)
    cudaFuncSetAttribute(h_nt_mma_kernel<CC, CC / 32, false>,
                         cudaFuncAttributeMaxDynamicSharedMemorySize, H_SMEM);
    h_nt_mma_kernel<CC, CC / 32, false><<<dim3(NN / 128, CC / 128, BB), blk, H_SMEM>>>(
        wvh, xth, nullptr, vh, nullptr, 0, (long long)NN * CC, sX);

    // S = q^T @ k  (split-fp16 mma, fp32-grade accuracy)
    cudaFuncSetAttribute(s_mma_kernel,
                         cudaFuncAttributeMaxDynamicSharedMemorySize, S_SMEM);
    s_mma_kernel<<<dim3(NN / 128, NN / 128, BB), blk, S_SMEM>>>(
        qth, qtl, kth, ktl, s);

    // P = softmax(S), emitted fp16 (6 rows per block)
    softmax_rows<<<BB * NN / SMR, 256>>>(s, ph);

    // out = gamma * (V @ P^T) + x  (fp16 mma, round-13 proven config)
    cudaFuncSetAttribute(h_nt_mma_kernel<NN, NN / 32, true>,
                         cudaFuncAttributeMaxDynamicSharedMemorySize, H_SMEM);
    h_nt_mma_kernel<NN, NN / 32, true><<<dim3(NN / 128, CC / 128, BB), blk, H_SMEM>>>(
        vh, ph, x, out, gamma, sX, (long long)NN * NN, sX);
}